// round 2
// baseline (speedup 1.0000x reference)
#include <cuda_runtime.h>
#include <math.h>
#include <stdint.h>

#define N 6144
#define D 128
#define INV_TAU 10.0f

// ---------------- device scratch ----------------
__device__ float g_Fn[N * D];
__device__ float g_Mn[N * D];
__device__ float g_Pn[N * D];
__device__ float g_repr[2][N * D];
__device__ float g_rowsum[2][N];
__device__ float g_pos[2][N];
__device__ float g_sumall[2][N];
__device__ float g_weights[N * 2];
__device__ float g_loss_acc;

// ---------------- packed f32x2 helpers ----------------
__device__ __forceinline__ unsigned long long pk2(float a, float b) {
    unsigned long long r;
    asm("mov.b64 %0, {%1,%2};" : "=l"(r) : "f"(a), "f"(b));
    return r;
}
__device__ __forceinline__ void ffma2(unsigned long long& d,
                                      unsigned long long a,
                                      unsigned long long b) {
    asm("fma.rn.f32x2 %0, %1, %2, %0;" : "+l"(d) : "l"(a), "l"(b));
}

// ---------------- K0: zero accumulators ----------------
__global__ void k_zero() {
    int idx = blockIdx.x * blockDim.x + threadIdx.x;
    if (idx < 2 * N) g_sumall[idx / N][idx % N] = 0.0f;
    if (idx == 0) g_loss_acc = 0.0f;
}

// ---------------- K1: L2 normalize ----------------
__global__ void k_normalize(const float* __restrict__ embF,
                            const float* __restrict__ embM,
                            const float* __restrict__ embP) {
    int i = blockIdx.x;
    int which = blockIdx.y;
    const float* src = (which == 0) ? embF : (which == 1) ? embM : embP;
    float* dst = (which == 0) ? g_Fn : (which == 1) ? g_Mn : g_Pn;
    int t = threadIdx.x;  // 128
    float v = src[(size_t)i * D + t];
    __shared__ float red[128];
    red[t] = v * v;
    __syncthreads();
#pragma unroll
    for (int s = 64; s > 0; s >>= 1) {
        if (t < s) red[t] += red[t + s];
        __syncthreads();
    }
    float norm = fmaxf(sqrtf(red[0]), 1e-12f);
    dst[(size_t)i * D + t] = v / norm;
}

// ---------------- K2: adjacency scan -> repr, rowsum, pos ----------------
#define MAXNZ 768
__global__ __launch_bounds__(128) void k_repr_pos(
    const float* __restrict__ FM_adj, const float* __restrict__ FP_adj,
    const float* __restrict__ embM, const float* __restrict__ embP) {
    int i = blockIdx.x;
    int w = blockIdx.y;
    const float* adj = (w == 0) ? FM_adj : FP_adj;
    const float* emb = (w == 0) ? embM : embP;
    const float* nrm = (w == 0) ? g_Mn : g_Pn;
    int t = threadIdx.x;

    __shared__ int s_idx[MAXNZ];
    __shared__ float s_val[MAXNZ];
    __shared__ int s_cnt;
    __shared__ float s_rowsum;
    __shared__ float s_pos;
    __shared__ float s_F[D];

    if (t == 0) { s_cnt = 0; s_rowsum = 0.0f; s_pos = 0.0f; }
    s_F[t] = g_Fn[(size_t)i * D + t];
    __syncthreads();

    const float4* arow = (const float4*)(adj + (size_t)i * N);
    float myrs = 0.0f;
#pragma unroll 4
    for (int c = t; c < N / 4; c += 128) {
        float4 v = __ldcs(&arow[c]);  // streaming: adjacency is read once
        if (v.x != 0.0f) { int p = atomicAdd(&s_cnt, 1); if (p < MAXNZ) { s_idx[p] = c * 4 + 0; s_val[p] = v.x; } myrs += v.x; }
        if (v.y != 0.0f) { int p = atomicAdd(&s_cnt, 1); if (p < MAXNZ) { s_idx[p] = c * 4 + 1; s_val[p] = v.y; } myrs += v.y; }
        if (v.z != 0.0f) { int p = atomicAdd(&s_cnt, 1); if (p < MAXNZ) { s_idx[p] = c * 4 + 2; s_val[p] = v.z; } myrs += v.z; }
        if (v.w != 0.0f) { int p = atomicAdd(&s_cnt, 1); if (p < MAXNZ) { s_idx[p] = c * 4 + 3; s_val[p] = v.w; } myrs += v.w; }
    }
    atomicAdd(&s_rowsum, myrs);
    __syncthreads();

    int cnt = min(s_cnt, MAXNZ);
    float rs = s_rowsum;
    float denom = fmaxf(rs, 1.0f);

    float acc = 0.0f;
    for (int e = 0; e < cnt; ++e)
        acc += s_val[e] * emb[(size_t)s_idx[e] * D + t];
    g_repr[w][(size_t)i * D + t] = acc / denom;
    if (t == 0) g_rowsum[w][i] = rs;

    int lane = t & 31, warp = t >> 5;
    float lp = 0.0f;
    for (int e = warp; e < cnt; e += 4) {
        int j = s_idx[e];
        const float* nr = nrm + (size_t)j * D;
        float p = s_F[lane] * nr[lane]
                + s_F[lane + 32] * nr[lane + 32]
                + s_F[lane + 64] * nr[lane + 64]
                + s_F[lane + 96] * nr[lane + 96];
#pragma unroll
        for (int o = 16; o; o >>= 1) p += __shfl_xor_sync(0xffffffffu, p, o);
        if (lane == 0) lp += s_val[e] * __expf(p * INV_TAU);
    }
    if (lane == 0) atomicAdd(&s_pos, lp);
    __syncthreads();
    if (t == 0) g_pos[w][i] = s_pos;
}

// ---------------- K3: dense sim row-sum via packed f32x2 FMA ----------------
// acc lanes pack {M, P}: acc += {a,a} * {bM,bP}. F tile (full K) duplicated
// {a,a} in smem; M/P interleaved {m,p} k-fast. Padded strides keep LDS at the
// wavefront floor.
#define BM 64
#define BN 64
#define BK 32
#define JT 16
#define JCH 6
#define FS_LD 130  // float2 per F row: 128 k + pad 2  (stride 1040 B ≡ 4 words mod 32)
#define MP_LD 34   // float2 per MP row: 32 k + pad 2  (stride 272 B  ≡ 4 words mod 32)

__global__ __launch_bounds__(256, 2) void k_simsum() {
    extern __shared__ float2 smdyn[];
    float2(*Fs2)[FS_LD] = (float2(*)[FS_LD])smdyn;                  // [BM][130] {a,a}
    float2(*MPs)[MP_LD] = (float2(*)[MP_LD])(smdyn + BM * FS_LD);   // [BN][34]  {m,p}
    __shared__ float redM[BM], redP[BM];

    const int tid = threadIdx.x;
    const int tx = tid & 15, ty = tid >> 4;
    const int i0 = blockIdx.x * BM;

    // Load F tile once for all K (duplicated packs).
#pragma unroll
    for (int p = 0; p < 8; ++p) {
        int s = tid + p * 256;
        int r = s >> 5, q = s & 31;
        float4 a = *(const float4*)&g_Fn[(size_t)(i0 + r) * D + 4 * q];
        *(ulonglong2*)&Fs2[r][4 * q]     = make_ulonglong2(pk2(a.x, a.x), pk2(a.y, a.y));
        *(ulonglong2*)&Fs2[r][4 * q + 2] = make_ulonglong2(pk2(a.z, a.z), pk2(a.w, a.w));
    }

    float sM[4] = {0, 0, 0, 0}, sP[4] = {0, 0, 0, 0};

#pragma unroll 1
    for (int jt = 0; jt < JT; ++jt) {
        int j0 = (blockIdx.y * JT + jt) * BN;
        unsigned long long acc[4][4];
#pragma unroll
        for (int m = 0; m < 4; ++m)
#pragma unroll
            for (int n = 0; n < 4; ++n) acc[m][n] = 0ull;

#pragma unroll 1
        for (int kc = 0; kc < D; kc += BK) {
            __syncthreads();
#pragma unroll
            for (int p = 0; p < 2; ++p) {
                int s = tid + p * 256;
                int r = s >> 3, q = s & 7;
                float4 mv = *(const float4*)&g_Mn[(size_t)(j0 + r) * D + kc + 4 * q];
                float4 pv = *(const float4*)&g_Pn[(size_t)(j0 + r) * D + kc + 4 * q];
                *(ulonglong2*)&MPs[r][4 * q]     = make_ulonglong2(pk2(mv.x, pv.x), pk2(mv.y, pv.y));
                *(ulonglong2*)&MPs[r][4 * q + 2] = make_ulonglong2(pk2(mv.z, pv.z), pk2(mv.w, pv.w));
            }
            __syncthreads();

#pragma unroll 2
            for (int kk = 0; kk < BK; kk += 2) {
                ulonglong2 A0 = *(const ulonglong2*)&Fs2[ty * 4 + 0][kc + kk];
                ulonglong2 A1 = *(const ulonglong2*)&Fs2[ty * 4 + 1][kc + kk];
                ulonglong2 A2 = *(const ulonglong2*)&Fs2[ty * 4 + 2][kc + kk];
                ulonglong2 A3 = *(const ulonglong2*)&Fs2[ty * 4 + 3][kc + kk];
                ulonglong2 B0 = *(const ulonglong2*)&MPs[tx + 0][kk];
                ulonglong2 B1 = *(const ulonglong2*)&MPs[tx + 16][kk];
                ulonglong2 B2 = *(const ulonglong2*)&MPs[tx + 32][kk];
                ulonglong2 B3 = *(const ulonglong2*)&MPs[tx + 48][kk];
                ffma2(acc[0][0], A0.x, B0.x); ffma2(acc[0][0], A0.y, B0.y);
                ffma2(acc[0][1], A0.x, B1.x); ffma2(acc[0][1], A0.y, B1.y);
                ffma2(acc[0][2], A0.x, B2.x); ffma2(acc[0][2], A0.y, B2.y);
                ffma2(acc[0][3], A0.x, B3.x); ffma2(acc[0][3], A0.y, B3.y);
                ffma2(acc[1][0], A1.x, B0.x); ffma2(acc[1][0], A1.y, B0.y);
                ffma2(acc[1][1], A1.x, B1.x); ffma2(acc[1][1], A1.y, B1.y);
                ffma2(acc[1][2], A1.x, B2.x); ffma2(acc[1][2], A1.y, B2.y);
                ffma2(acc[1][3], A1.x, B3.x); ffma2(acc[1][3], A1.y, B3.y);
                ffma2(acc[2][0], A2.x, B0.x); ffma2(acc[2][0], A2.y, B0.y);
                ffma2(acc[2][1], A2.x, B1.x); ffma2(acc[2][1], A2.y, B1.y);
                ffma2(acc[2][2], A2.x, B2.x); ffma2(acc[2][2], A2.y, B2.y);
                ffma2(acc[2][3], A2.x, B3.x); ffma2(acc[2][3], A2.y, B3.y);
                ffma2(acc[3][0], A3.x, B0.x); ffma2(acc[3][0], A3.y, B0.y);
                ffma2(acc[3][1], A3.x, B1.x); ffma2(acc[3][1], A3.y, B1.y);
                ffma2(acc[3][2], A3.x, B2.x); ffma2(acc[3][2], A3.y, B2.y);
                ffma2(acc[3][3], A3.x, B3.x); ffma2(acc[3][3], A3.y, B3.y);
            }
        }

        // epilogue: exp + partial row sums
#pragma unroll
        for (int m = 0; m < 4; ++m) {
            float tM = 0.0f, tP = 0.0f;
#pragma unroll
            for (int n = 0; n < 4; ++n) {
                float2 v = *(float2*)&acc[m][n];
                tM += __expf(v.x * INV_TAU);
                tP += __expf(v.y * INV_TAU);
            }
            sM[m] += tM;
            sP[m] += tP;
        }
    }

    if (tid < BM) { redM[tid] = 0.0f; redP[tid] = 0.0f; }
    __syncthreads();
#pragma unroll
    for (int m = 0; m < 4; ++m) {
        atomicAdd(&redM[ty * 4 + m], sM[m]);
        atomicAdd(&redP[ty * 4 + m], sP[m]);
    }
    __syncthreads();
    if (tid < BM) {
        atomicAdd(&g_sumall[0][i0 + tid], redM[tid]);
        atomicAdd(&g_sumall[1][i0 + tid], redP[tid]);
    }
}

// ---------------- K4: MLP + softmax (W1 staged once per block) ----------------
#define MLP_ROWS 64
__global__ __launch_bounds__(256) void k_mlp(const float* __restrict__ W1,
                                             const float* __restrict__ b1,
                                             const float* __restrict__ W2,
                                             const float* __restrict__ b2,
                                             float* __restrict__ out_weights) {
    extern __shared__ float smf[];
    float* W1s = smf;                   // 256*128
    float* feats = smf + 256 * 128;     // MLP_ROWS*256
    __shared__ float srow[2][2];

    int i0 = blockIdx.x * MLP_ROWS;
    int tid = threadIdx.x;

#pragma unroll 8
    for (int p = 0; p < 128; ++p) W1s[tid + p * 256] = W1[tid + p * 256];
#pragma unroll 4
    for (int p = 0; p < MLP_ROWS; ++p) {
        int s = tid + p * 256;
        int r = s >> 8, k = s & 255;
        feats[s] = (k < 128) ? g_repr[0][(size_t)(i0 + r) * D + k]
                             : g_repr[1][(size_t)(i0 + r) * D + (k - 128)];
    }
    __syncthreads();

    int c = tid & 127, half = tid >> 7;
    int lane = tid & 31;
    float b1c = b1[c], w20 = W2[2 * c], w21 = W2[2 * c + 1];

    for (int rp = 0; rp < MLP_ROWS / 2; ++rp) {
        const float* fr = feats + (rp * 2 + half) * 256;
        float h0 = 0, h1 = 0, h2 = 0, h3 = 0;
#pragma unroll 8
        for (int k = 0; k < 256; k += 4) {
            h0 = fmaf(fr[k + 0], W1s[(k + 0) * 128 + c], h0);
            h1 = fmaf(fr[k + 1], W1s[(k + 1) * 128 + c], h1);
            h2 = fmaf(fr[k + 2], W1s[(k + 2) * 128 + c], h2);
            h3 = fmaf(fr[k + 3], W1s[(k + 3) * 128 + c], h3);
        }
        float h = fmaxf((h0 + h1) + (h2 + h3) + b1c, 0.0f);
        float p0 = h * w20, p1 = h * w21;
#pragma unroll
        for (int o = 16; o; o >>= 1) {
            p0 += __shfl_xor_sync(0xffffffffu, p0, o);
            p1 += __shfl_xor_sync(0xffffffffu, p1, o);
        }
        if (tid < 4) srow[tid >> 1][tid & 1] = 0.0f;
        __syncthreads();
        if (lane == 0) {
            atomicAdd(&srow[half][0], p0);
            atomicAdd(&srow[half][1], p1);
        }
        __syncthreads();
        if (tid < 2) {
            int row = i0 + rp * 2 + tid;
            float o0 = srow[tid][0] + b2[0];
            float o1 = srow[tid][1] + b2[1];
            float mx = fmaxf(o0, o1);
            float e0 = expf(o0 - mx), e1 = expf(o1 - mx);
            float inv = 1.0f / (e0 + e1);
            float w0 = e0 * inv, w1 = e1 * inv;
            g_weights[2 * row] = w0;
            g_weights[2 * row + 1] = w1;
            out_weights[2 * row] = w0;
            out_weights[2 * row + 1] = w1;
        }
        __syncthreads();
    }
}

// ---------------- K5: loss reduction ----------------
__global__ __launch_bounds__(256) void k_loss() {
    int idx = blockIdx.x * blockDim.x + threadIdx.x;
    int stride = gridDim.x * blockDim.x;
    float term = 0.0f;
    for (int i = idx; i < N; i += stride) {
        float w0 = g_weights[2 * i], w1 = g_weights[2 * i + 1];
        float pm = g_pos[0][i], pp = g_pos[1][i];
        float sm = g_sumall[0][i], sp = g_sumall[1][i];
        float wp = w0 * pm + w1 * pp;
        float wn = w0 * (sm - pm) + w1 * (sp - pp);
        float nei = fmaxf(g_rowsum[0][i] + g_rowsum[1][i], 1.0f);
        float ratio = wp / (wp + wn) / nei;
        ratio = fmaxf(ratio, 1e-10f);
        term += -logf(ratio);
    }
    __shared__ float red[256];
    red[threadIdx.x] = term;
    __syncthreads();
#pragma unroll
    for (int s = 128; s > 0; s >>= 1) {
        if (threadIdx.x < s) red[threadIdx.x] += red[threadIdx.x + s];
        __syncthreads();
    }
    if (threadIdx.x == 0) atomicAdd(&g_loss_acc, red[0]);
}

__global__ void k_finalize(float* __restrict__ out) {
    out[0] = g_loss_acc / (float)N;
}

// ---------------- launch ----------------
extern "C" void kernel_launch(void* const* d_in, const int* in_sizes, int n_in,
                              void* d_out, int out_size) {
    const float* embF = (const float*)d_in[0];
    const float* embM = (const float*)d_in[1];
    const float* embP = (const float*)d_in[2];
    const float* FM_adj = (const float*)d_in[3];
    const float* FP_adj = (const float*)d_in[4];
    const float* W1 = (const float*)d_in[5];
    const float* b1 = (const float*)d_in[6];
    const float* W2 = (const float*)d_in[7];
    const float* b2 = (const float*)d_in[8];
    float* out = (float*)d_out;

    const int simsum_smem = (BM * FS_LD + BN * MP_LD) * (int)sizeof(float2);  // 83968
    const int mlp_smem = (256 * 128 + MLP_ROWS * 256) * (int)sizeof(float);   // 196608
    cudaFuncSetAttribute(k_simsum, cudaFuncAttributeMaxDynamicSharedMemorySize, simsum_smem);
    cudaFuncSetAttribute(k_mlp, cudaFuncAttributeMaxDynamicSharedMemorySize, mlp_smem);

    k_zero<<<(2 * N + 255) / 256, 256>>>();
    k_normalize<<<dim3(N, 3), 128>>>(embF, embM, embP);
    k_simsum<<<dim3(N / BM, JCH), 256, simsum_smem>>>();
    k_repr_pos<<<dim3(N, 2), 128>>>(FM_adj, FP_adj, embM, embP);
    k_mlp<<<N / MLP_ROWS, 256, mlp_smem>>>(W1, b1, W2, b2, out + 1);
    k_loss<<<24, 256>>>();
    k_finalize<<<1, 1>>>(out);
}

// round 4
// speedup vs baseline: 2.0851x; 2.0851x over previous
#include <cuda_runtime.h>
#include <cuda_bf16.h>
#include <math.h>
#include <stdint.h>

#define N 6144
#define D 128
#define INV_TAU 10.0f
#define NB (2 * N)
#define NTILES 96          // 12288 / 128
#define JSPLIT 6
#define TILES_PER (NTILES / JSPLIT)  // 16

// ---------------- device scratch ----------------
__device__ float g_Fn[N * D];
__device__ float g_Mn[N * D];
__device__ float g_Pn[N * D];
__device__ __nv_bfloat16 g_Ahi[N * D];
__device__ __nv_bfloat16 g_Alo[N * D];
__device__ __nv_bfloat16 g_Bhi[NB * D];
__device__ __nv_bfloat16 g_Blo[NB * D];
__device__ float g_repr[2][N * D];
__device__ float g_rowsum[2][N];
__device__ float g_pos[2][N];
__device__ float g_sumall[2][N];
__device__ float g_weights[N * 2];
__device__ float g_loss_acc;

// ---------------- PTX helpers (all sm_80+/sm_90 features, no 'a'-gated ops) ----
__device__ __forceinline__ uint32_t s2u(const void* p) {
    uint32_t a;
    asm("{ .reg .u64 t; cvta.to.shared.u64 t, %1; cvt.u32.u64 %0, t; }" : "=r"(a) : "l"(p));
    return a;
}
__device__ __forceinline__ void cp16(uint32_t dst, const void* src) {
    asm volatile("cp.async.cg.shared.global [%0], [%1], 16;" :: "r"(dst), "l"(src));
}
#define CP_COMMIT() asm volatile("cp.async.commit_group;")
__device__ __forceinline__ void ldsm4(uint32_t* r, uint32_t addr) {
    asm volatile("ldmatrix.sync.aligned.m8n8.x4.shared.b16 {%0,%1,%2,%3}, [%4];"
                 : "=r"(r[0]), "=r"(r[1]), "=r"(r[2]), "=r"(r[3]) : "r"(addr));
}
__device__ __forceinline__ void mma_bf16(float* d, const uint32_t* a, uint32_t b0, uint32_t b1) {
    asm volatile(
        "mma.sync.aligned.m16n8k16.row.col.f32.bf16.bf16.f32 "
        "{%0,%1,%2,%3}, {%4,%5,%6,%7}, {%8,%9}, {%0,%1,%2,%3};"
        : "+f"(d[0]), "+f"(d[1]), "+f"(d[2]), "+f"(d[3])
        : "r"(a[0]), "r"(a[1]), "r"(a[2]), "r"(a[3]), "r"(b0), "r"(b1));
}

// SMEM tile geometry: 128 rows x 136 bf16 (stride 272 B; +8 pad -> conflict-free)
#define TSTRIDE 272
#define TILE_BYTES (128 * TSTRIDE)          // 34816
static constexpr int OFF_AHI = 0;
static constexpr int OFF_ALO = TILE_BYTES;
static constexpr int OFF_B = 2 * TILE_BYTES;  // B[buf][hl]: buf*2*TILE + hl*TILE
static constexpr int SIMTC_SMEM = 6 * TILE_BYTES;  // 208896

// ---------------- K0: zero ----------------
__global__ void k_zero() {
    int idx = blockIdx.x * blockDim.x + threadIdx.x;
    if (idx < 2 * N) g_sumall[idx / N][idx % N] = 0.0f;
    if (idx == 0) g_loss_acc = 0.0f;
}

// ---------------- K1: normalize + bf16 hi/lo split ----------------
__global__ void k_normalize(const float* __restrict__ embF,
                            const float* __restrict__ embM,
                            const float* __restrict__ embP) {
    int i = blockIdx.x;
    int which = blockIdx.y;
    const float* src = (which == 0) ? embF : (which == 1) ? embM : embP;
    float* dst = (which == 0) ? g_Fn : (which == 1) ? g_Mn : g_Pn;
    int t = threadIdx.x;  // 128
    float v = src[(size_t)i * D + t];
    __shared__ float red[128];
    red[t] = v * v;
    __syncthreads();
#pragma unroll
    for (int s = 64; s > 0; s >>= 1) {
        if (t < s) red[t] += red[t + s];
        __syncthreads();
    }
    float norm = fmaxf(sqrtf(red[0]), 1e-12f);
    float nv = v / norm;
    dst[(size_t)i * D + t] = nv;
    __nv_bfloat16 hi = __float2bfloat16(nv);
    __nv_bfloat16 lo = __float2bfloat16(nv - __bfloat162float(hi));
    if (which == 0) {
        g_Ahi[i * D + t] = hi;
        g_Alo[i * D + t] = lo;
    } else {
        int r = (which == 1) ? i : (N + i);
        g_Bhi[r * D + t] = hi;
        g_Blo[r * D + t] = lo;
    }
}

// ---------------- K2: adjacency scan (ballot compaction) ----------------
#define MAXNZ 768
__global__ __launch_bounds__(128) void k_repr_pos(
    const float* __restrict__ FM_adj, const float* __restrict__ FP_adj,
    const float* __restrict__ embM, const float* __restrict__ embP) {
    int i = blockIdx.x;
    int w = blockIdx.y;
    const float* adj = (w == 0) ? FM_adj : FP_adj;
    const float* emb = (w == 0) ? embM : embP;
    const float* nrm = (w == 0) ? g_Mn : g_Pn;
    int t = threadIdx.x;
    int lane = t & 31;

    __shared__ int s_idx[MAXNZ];
    __shared__ float s_val[MAXNZ];
    __shared__ int s_cnt;
    __shared__ float s_rowsum;
    __shared__ float s_pos;
    __shared__ float s_F[D];

    if (t == 0) { s_cnt = 0; s_rowsum = 0.0f; s_pos = 0.0f; }
    s_F[t] = g_Fn[(size_t)i * D + t];
    __syncthreads();

    const float4* arow = (const float4*)(adj + (size_t)i * N);
    unsigned lt = (1u << lane) - 1u;
    float myrs = 0.0f;
    for (int c = t; c < N / 4; c += 128) {
        float4 v = __ldcs(&arow[c]);
        float comp[4] = {v.x, v.y, v.z, v.w};
#pragma unroll
        for (int q = 0; q < 4; ++q) {
            float x = comp[q];
            unsigned m = __ballot_sync(0xffffffffu, x != 0.0f);
            if (m) {
                int base = 0;
                if (lane == 0) base = atomicAdd(&s_cnt, __popc(m));
                base = __shfl_sync(0xffffffffu, base, 0);
                if (x != 0.0f) {
                    int p = base + __popc(m & lt);
                    if (p < MAXNZ) { s_idx[p] = c * 4 + q; s_val[p] = x; }
                    myrs += x;
                }
            }
        }
    }
#pragma unroll
    for (int o = 16; o; o >>= 1) myrs += __shfl_xor_sync(0xffffffffu, myrs, o);
    if (lane == 0) atomicAdd(&s_rowsum, myrs);
    __syncthreads();

    int cnt = min(s_cnt, MAXNZ);
    float rs = s_rowsum;
    float denom = fmaxf(rs, 1.0f);

    float acc = 0.0f;
    for (int e = 0; e < cnt; ++e)
        acc += s_val[e] * emb[(size_t)s_idx[e] * D + t];
    g_repr[w][(size_t)i * D + t] = acc / denom;
    if (t == 0) g_rowsum[w][i] = rs;

    int warp = t >> 5;
    float lp = 0.0f;
    for (int e = warp; e < cnt; e += 4) {
        int j = s_idx[e];
        const float* nr = nrm + (size_t)j * D;
        float p = s_F[lane] * nr[lane]
                + s_F[lane + 32] * nr[lane + 32]
                + s_F[lane + 64] * nr[lane + 64]
                + s_F[lane + 96] * nr[lane + 96];
#pragma unroll
        for (int o = 16; o; o >>= 1) p += __shfl_xor_sync(0xffffffffu, p, o);
        if (lane == 0) lp += s_val[e] * __expf(p * INV_TAU);
    }
    if (lane == 0) atomicAdd(&s_pos, lp);
    __syncthreads();
    if (t == 0) g_pos[w][i] = s_pos;
}

// ---------------- K3: HMMA (mma.sync bf16) sim row sums ----------------
// D[i,j] = Ahi*Bhi + Ahi*Blo + Alo*Bhi accumulated in fp32; epilogue
// exp(d/tau) row-sums. Block 256thr (8 warps, 4x2), block tile 128x128,
// warp tile 32x64. B double-buffered via cp.async.
__device__ __forceinline__ void load_tile(uint32_t dst, const __nv_bfloat16* src,
                                          int row0, int tid) {
#pragma unroll
    for (int p = 0; p < 8; ++p) {
        int idx = tid + (p << 8);
        int r = idx >> 4, c = idx & 15;
        cp16(dst + r * TSTRIDE + c * 16, src + (size_t)(row0 + r) * D + c * 8);
    }
}

__global__ __launch_bounds__(256, 1) void k_simsum_mma() {
    extern __shared__ __align__(16) char dsm[];
    const uint32_t smb = s2u(dsm);
    const int tid = threadIdx.x;
    const int wid = tid >> 5;
    const int lane = tid & 31;
    const int wm = (wid & 3) * 32;   // warp m offset
    const int wn = (wid >> 2) * 64;  // warp n offset
    const int i0 = blockIdx.x * 128;
    const int tbase = blockIdx.y * TILES_PER;
    const int tgt = (blockIdx.y < JSPLIT / 2) ? 0 : 1;

    // ldmatrix lane-address offsets (bytes)
    const uint32_t aoff = (uint32_t)(lane & 15) * TSTRIDE + (uint32_t)(lane >> 4) * 16;
    const uint32_t boff = (uint32_t)(((lane >> 3) & 1) * 8 + (lane & 7)) * TSTRIDE
                        + (uint32_t)(lane >> 4) * 16;

    // prologue: G0 = A(hi+lo) + B0(hi+lo); G1 = B1(hi+lo)
    load_tile(smb + OFF_AHI, g_Ahi, i0, tid);
    load_tile(smb + OFF_ALO, g_Alo, i0, tid);
    load_tile(smb + OFF_B, g_Bhi, tbase * 128, tid);
    load_tile(smb + OFF_B + TILE_BYTES, g_Blo, tbase * 128, tid);
    CP_COMMIT();
    load_tile(smb + OFF_B + 2 * TILE_BYTES, g_Bhi, (tbase + 1) * 128, tid);
    load_tile(smb + OFF_B + 3 * TILE_BYTES, g_Blo, (tbase + 1) * 128, tid);
    CP_COMMIT();

    float rsum[2][2] = {{0, 0}, {0, 0}};  // [mfrag][row half] running row sums

    for (int t = 0; t < TILES_PER; ++t) {
        const int buf = t & 1;
        asm volatile("cp.async.wait_group 1;");
        __syncthreads();

        const uint32_t bhi = smb + OFF_B + buf * 2 * TILE_BYTES;
        const uint32_t blo = bhi + TILE_BYTES;

        float acc[2][8][4];
#pragma unroll
        for (int f = 0; f < 2; ++f)
#pragma unroll
            for (int n = 0; n < 8; ++n)
#pragma unroll
                for (int r = 0; r < 4; ++r) acc[f][n][r] = 0.0f;

#pragma unroll
        for (int ks = 0; ks < 8; ++ks) {
            uint32_t ah[2][4], al[2][4];
#pragma unroll
            for (int f = 0; f < 2; ++f) {
                ldsm4(ah[f], smb + OFF_AHI + (wm + f * 16) * TSTRIDE + ks * 32 + aoff);
                ldsm4(al[f], smb + OFF_ALO + (wm + f * 16) * TSTRIDE + ks * 32 + aoff);
            }
#pragma unroll
            for (int g = 0; g < 4; ++g) {
                uint32_t bh[4], bl[4];
                ldsm4(bh, bhi + (wn + g * 16) * TSTRIDE + ks * 32 + boff);
                ldsm4(bl, blo + (wn + g * 16) * TSTRIDE + ks * 32 + boff);
#pragma unroll
                for (int f = 0; f < 2; ++f) {
                    mma_bf16(acc[f][2 * g], ah[f], bh[0], bh[2]);
                    mma_bf16(acc[f][2 * g + 1], ah[f], bh[1], bh[3]);
                    mma_bf16(acc[f][2 * g], al[f], bh[0], bh[2]);
                    mma_bf16(acc[f][2 * g + 1], al[f], bh[1], bh[3]);
                    mma_bf16(acc[f][2 * g], ah[f], bl[0], bl[2]);
                    mma_bf16(acc[f][2 * g + 1], ah[f], bl[1], bl[3]);
                }
            }
        }

        __syncthreads();
        if (t + 2 < TILES_PER) {
            int j0 = (tbase + t + 2) * 128;
            load_tile(smb + OFF_B + buf * 2 * TILE_BYTES, g_Bhi, j0, tid);
            load_tile(smb + OFF_B + buf * 2 * TILE_BYTES + TILE_BYTES, g_Blo, j0, tid);
        }
        CP_COMMIT();

        // epilogue: exp + accumulate per-row partial sums
#pragma unroll
        for (int f = 0; f < 2; ++f) {
            float e0 = 0.0f, e1 = 0.0f;
#pragma unroll
            for (int n = 0; n < 8; ++n) {
                e0 += __expf(acc[f][n][0] * INV_TAU) + __expf(acc[f][n][1] * INV_TAU);
                e1 += __expf(acc[f][n][2] * INV_TAU) + __expf(acc[f][n][3] * INV_TAU);
            }
            rsum[f][0] += e0;
            rsum[f][1] += e1;
        }
    }

    // quad-reduce (4 threads share a row) then global atomic
#pragma unroll
    for (int f = 0; f < 2; ++f)
#pragma unroll
        for (int r = 0; r < 2; ++r) {
            float v = rsum[f][r];
            v += __shfl_xor_sync(0xffffffffu, v, 1);
            v += __shfl_xor_sync(0xffffffffu, v, 2);
            if ((lane & 3) == 0) {
                int row = i0 + wm + f * 16 + (lane >> 2) + r * 8;
                atomicAdd(&g_sumall[tgt][row], v);
            }
        }
}

// ---------------- K4: MLP + softmax ----------------
#define MLP_ROWS 64
__global__ __launch_bounds__(256) void k_mlp(const float* __restrict__ W1,
                                             const float* __restrict__ b1,
                                             const float* __restrict__ W2,
                                             const float* __restrict__ b2,
                                             float* __restrict__ out_weights) {
    extern __shared__ float smf[];
    float* W1s = smf;
    float* feats = smf + 256 * 128;
    __shared__ float srow[2][2];

    int i0 = blockIdx.x * MLP_ROWS;
    int tid = threadIdx.x;

#pragma unroll 8
    for (int p = 0; p < 128; ++p) W1s[tid + p * 256] = W1[tid + p * 256];
#pragma unroll 4
    for (int p = 0; p < MLP_ROWS; ++p) {
        int s = tid + p * 256;
        int r = s >> 8, k = s & 255;
        feats[s] = (k < 128) ? g_repr[0][(size_t)(i0 + r) * D + k]
                             : g_repr[1][(size_t)(i0 + r) * D + (k - 128)];
    }
    __syncthreads();

    int c = tid & 127, half = tid >> 7;
    int lane = tid & 31;
    float b1c = b1[c], w20 = W2[2 * c], w21 = W2[2 * c + 1];

    for (int rp = 0; rp < MLP_ROWS / 2; ++rp) {
        const float* fr = feats + (rp * 2 + half) * 256;
        float h0 = 0, h1 = 0, h2 = 0, h3 = 0;
#pragma unroll 8
        for (int k = 0; k < 256; k += 4) {
            h0 = fmaf(fr[k + 0], W1s[(k + 0) * 128 + c], h0);
            h1 = fmaf(fr[k + 1], W1s[(k + 1) * 128 + c], h1);
            h2 = fmaf(fr[k + 2], W1s[(k + 2) * 128 + c], h2);
            h3 = fmaf(fr[k + 3], W1s[(k + 3) * 128 + c], h3);
        }
        float h = fmaxf((h0 + h1) + (h2 + h3) + b1c, 0.0f);
        float p0 = h * w20, p1 = h * w21;
#pragma unroll
        for (int o = 16; o; o >>= 1) {
            p0 += __shfl_xor_sync(0xffffffffu, p0, o);
            p1 += __shfl_xor_sync(0xffffffffu, p1, o);
        }
        if (tid < 4) srow[tid >> 1][tid & 1] = 0.0f;
        __syncthreads();
        if (lane == 0) {
            atomicAdd(&srow[half][0], p0);
            atomicAdd(&srow[half][1], p1);
        }
        __syncthreads();
        if (tid < 2) {
            int row = i0 + rp * 2 + tid;
            float o0 = srow[tid][0] + b2[0];
            float o1 = srow[tid][1] + b2[1];
            float mx = fmaxf(o0, o1);
            float e0 = expf(o0 - mx), e1 = expf(o1 - mx);
            float inv = 1.0f / (e0 + e1);
            float w0 = e0 * inv, w1 = e1 * inv;
            g_weights[2 * row] = w0;
            g_weights[2 * row + 1] = w1;
            out_weights[2 * row] = w0;
            out_weights[2 * row + 1] = w1;
        }
        __syncthreads();
    }
}

// ---------------- K5: loss ----------------
__global__ __launch_bounds__(256) void k_loss() {
    int idx = blockIdx.x * blockDim.x + threadIdx.x;
    int stride = gridDim.x * blockDim.x;
    float term = 0.0f;
    for (int i = idx; i < N; i += stride) {
        float w0 = g_weights[2 * i], w1 = g_weights[2 * i + 1];
        float pm = g_pos[0][i], pp = g_pos[1][i];
        float sm = g_sumall[0][i], sp = g_sumall[1][i];
        float wp = w0 * pm + w1 * pp;
        float wn = w0 * (sm - pm) + w1 * (sp - pp);
        float nei = fmaxf(g_rowsum[0][i] + g_rowsum[1][i], 1.0f);
        float ratio = wp / (wp + wn) / nei;
        ratio = fmaxf(ratio, 1e-10f);
        term += -logf(ratio);
    }
    __shared__ float red[256];
    red[threadIdx.x] = term;
    __syncthreads();
#pragma unroll
    for (int s = 128; s > 0; s >>= 1) {
        if (threadIdx.x < s) red[threadIdx.x] += red[threadIdx.x + s];
        __syncthreads();
    }
    if (threadIdx.x == 0) atomicAdd(&g_loss_acc, red[0]);
}

__global__ void k_finalize(float* __restrict__ out) {
    out[0] = g_loss_acc / (float)N;
}

// ---------------- launch ----------------
extern "C" void kernel_launch(void* const* d_in, const int* in_sizes, int n_in,
                              void* d_out, int out_size) {
    const float* embF = (const float*)d_in[0];
    const float* embM = (const float*)d_in[1];
    const float* embP = (const float*)d_in[2];
    const float* FM_adj = (const float*)d_in[3];
    const float* FP_adj = (const float*)d_in[4];
    const float* W1 = (const float*)d_in[5];
    const float* b1 = (const float*)d_in[6];
    const float* W2 = (const float*)d_in[7];
    const float* b2 = (const float*)d_in[8];
    float* out = (float*)d_out;

    const int mlp_smem = (256 * 128 + MLP_ROWS * 256) * (int)sizeof(float);
    cudaFuncSetAttribute(k_simsum_mma, cudaFuncAttributeMaxDynamicSharedMemorySize, SIMTC_SMEM);
    cudaFuncSetAttribute(k_mlp, cudaFuncAttributeMaxDynamicSharedMemorySize, mlp_smem);

    k_zero<<<(2 * N + 255) / 256, 256>>>();
    k_normalize<<<dim3(N, 3), 128>>>(embF, embM, embP);
    k_simsum_mma<<<dim3(N / 128, JSPLIT), 256, SIMTC_SMEM>>>();
    k_repr_pos<<<dim3(N, 2), 128>>>(FM_adj, FP_adj, embM, embP);
    k_mlp<<<N / MLP_ROWS, 256, mlp_smem>>>(W1, b1, W2, b2, out + 1);
    k_loss<<<24, 256>>>();
    k_finalize<<<1, 1>>>(out);
}

// round 5
// speedup vs baseline: 2.9189x; 1.3999x over previous
#include <cuda_runtime.h>
#include <cuda_bf16.h>
#include <math.h>
#include <stdint.h>

#define N 6144
#define D 128
#define INV_TAU 10.0f
#define NB (2 * N)
#define JSPLIT 6
#define TILES_PER 16   // 6*16*128 = 12288

// ---------------- device scratch ----------------
__device__ float g_Fn[N * D];
__device__ float g_Mn[N * D];
__device__ float g_Pn[N * D];
__device__ __nv_bfloat16 g_Abf[N * D];
__device__ __nv_bfloat16 g_Bbf[NB * D];
__device__ float g_repr[2][N * D];
__device__ float g_rowsum[2][N];
__device__ float g_pos[2][N];
__device__ float g_sumall[2][N];
__device__ float g_weights[N * 2];
__device__ float g_loss_acc;

// ---------------- PTX helpers ----------------
__device__ __forceinline__ uint32_t s2u(const void* p) {
    uint32_t a;
    asm("{ .reg .u64 t; cvta.to.shared.u64 t, %1; cvt.u32.u64 %0, t; }" : "=r"(a) : "l"(p));
    return a;
}
__device__ __forceinline__ void cp16(uint32_t dst, const void* src) {
    asm volatile("cp.async.cg.shared.global [%0], [%1], 16;" :: "r"(dst), "l"(src));
}
#define CP_COMMIT() asm volatile("cp.async.commit_group;")
__device__ __forceinline__ void ldsm4(uint32_t* r, uint32_t addr) {
    asm volatile("ldmatrix.sync.aligned.m8n8.x4.shared.b16 {%0,%1,%2,%3}, [%4];"
                 : "=r"(r[0]), "=r"(r[1]), "=r"(r[2]), "=r"(r[3]) : "r"(addr));
}
__device__ __forceinline__ void mma_bf16(float* d, const uint32_t* a, uint32_t b0, uint32_t b1) {
    asm volatile(
        "mma.sync.aligned.m16n8k16.row.col.f32.bf16.bf16.f32 "
        "{%0,%1,%2,%3}, {%4,%5,%6,%7}, {%8,%9}, {%0,%1,%2,%3};"
        : "+f"(d[0]), "+f"(d[1]), "+f"(d[2]), "+f"(d[3])
        : "r"(a[0]), "r"(a[1]), "r"(a[2]), "r"(a[3]), "r"(b0), "r"(b1));
}

// SMEM tile: 128 rows x 136 bf16 (stride 272 B, +8 pad -> conflict-free ldmatrix)
#define TSTRIDE 272
#define TILE_BYTES (128 * TSTRIDE)                 // 34816
static constexpr int OFF_A = 0;
static constexpr int OFF_B = TILE_BYTES;           // two buffers follow
static constexpr int SIMTC_SMEM = 3 * TILE_BYTES;  // 104448

// ---------------- K0: zero ----------------
__global__ void k_zero() {
    int idx = blockIdx.x * blockDim.x + threadIdx.x;
    if (idx < 2 * N) g_sumall[idx / N][idx % N] = 0.0f;
    if (idx == 0) g_loss_acc = 0.0f;
}

// ---------------- K1: normalize + bf16 cast ----------------
__global__ void k_normalize(const float* __restrict__ embF,
                            const float* __restrict__ embM,
                            const float* __restrict__ embP) {
    int i = blockIdx.x;
    int which = blockIdx.y;
    const float* src = (which == 0) ? embF : (which == 1) ? embM : embP;
    float* dst = (which == 0) ? g_Fn : (which == 1) ? g_Mn : g_Pn;
    int t = threadIdx.x;  // 128
    float v = src[(size_t)i * D + t];
    __shared__ float red[128];
    red[t] = v * v;
    __syncthreads();
#pragma unroll
    for (int s = 64; s > 0; s >>= 1) {
        if (t < s) red[t] += red[t + s];
        __syncthreads();
    }
    float norm = fmaxf(sqrtf(red[0]), 1e-12f);
    float nv = v / norm;
    dst[(size_t)i * D + t] = nv;
    __nv_bfloat16 h = __float2bfloat16(nv);
    if (which == 0) g_Abf[i * D + t] = h;
    else g_Bbf[((which == 1) ? i : (N + i)) * D + t] = h;
}

// ---------------- K2: adjacency scan (prefetch + ballot compaction) --------
#define MAXNZ 768
#define VPT 12  // (N/4)/128 float4 per thread
__global__ __launch_bounds__(128) void k_repr_pos(
    const float* __restrict__ FM_adj, const float* __restrict__ FP_adj,
    const float* __restrict__ embM, const float* __restrict__ embP) {
    int i = blockIdx.x;
    int w = blockIdx.y;
    const float* adj = (w == 0) ? FM_adj : FP_adj;
    const float* emb = (w == 0) ? embM : embP;
    const float* nrm = (w == 0) ? g_Mn : g_Pn;
    int t = threadIdx.x;
    int lane = t & 31;

    __shared__ int s_idx[MAXNZ];
    __shared__ float s_val[MAXNZ];
    __shared__ int s_cnt;
    __shared__ float s_rowsum;
    __shared__ float s_pos;
    __shared__ float s_F[D];

    if (t == 0) { s_cnt = 0; s_rowsum = 0.0f; s_pos = 0.0f; }
    s_F[t] = g_Fn[(size_t)i * D + t];

    const float4* arow = (const float4*)(adj + (size_t)i * N);
    float4 v[VPT];
#pragma unroll
    for (int q = 0; q < VPT; ++q) v[q] = __ldcs(&arow[t + q * 128]);
    __syncthreads();

    unsigned lt = (1u << lane) - 1u;
    float myrs = 0.0f;
#pragma unroll
    for (int q = 0; q < VPT; ++q) {
        int c = t + q * 128;
        float comp[4] = {v[q].x, v[q].y, v[q].z, v[q].w};
#pragma unroll
        for (int e = 0; e < 4; ++e) {
            float x = comp[e];
            unsigned m = __ballot_sync(0xffffffffu, x != 0.0f);
            if (m) {
                int base = 0;
                if (lane == 0) base = atomicAdd(&s_cnt, __popc(m));
                base = __shfl_sync(0xffffffffu, base, 0);
                if (x != 0.0f) {
                    int p = base + __popc(m & lt);
                    if (p < MAXNZ) { s_idx[p] = c * 4 + e; s_val[p] = x; }
                    myrs += x;
                }
            }
        }
    }
#pragma unroll
    for (int o = 16; o; o >>= 1) myrs += __shfl_xor_sync(0xffffffffu, myrs, o);
    if (lane == 0) atomicAdd(&s_rowsum, myrs);
    __syncthreads();

    int cnt = min(s_cnt, MAXNZ);
    float rs = s_rowsum;
    float denom = fmaxf(rs, 1.0f);

    float acc = 0.0f;
    for (int e = 0; e < cnt; ++e)
        acc += s_val[e] * emb[(size_t)s_idx[e] * D + t];
    g_repr[w][(size_t)i * D + t] = acc / denom;
    if (t == 0) g_rowsum[w][i] = rs;

    int warp = t >> 5;
    float lp = 0.0f;
    for (int e = warp; e < cnt; e += 4) {
        int j = s_idx[e];
        const float* nr = nrm + (size_t)j * D;
        float p = s_F[lane] * nr[lane]
                + s_F[lane + 32] * nr[lane + 32]
                + s_F[lane + 64] * nr[lane + 64]
                + s_F[lane + 96] * nr[lane + 96];
#pragma unroll
        for (int o = 16; o; o >>= 1) p += __shfl_xor_sync(0xffffffffu, p, o);
        if (lane == 0) lp += s_val[e] * __expf(p * INV_TAU);
    }
    if (lane == 0) atomicAdd(&s_pos, lp);
    __syncthreads();
    if (t == 0) g_pos[w][i] = s_pos;
}

// ---------------- K3: single-pass bf16 HMMA sim row sums ----------------
__device__ __forceinline__ void load_tile(uint32_t dst, const __nv_bfloat16* src,
                                          int row0, int tid) {
#pragma unroll
    for (int p = 0; p < 8; ++p) {
        int idx = tid + (p << 8);
        int r = idx >> 4, c = idx & 15;
        cp16(dst + r * TSTRIDE + c * 16, src + (size_t)(row0 + r) * D + c * 8);
    }
}

__global__ __launch_bounds__(256, 2) void k_simsum_mma() {
    extern __shared__ __align__(16) char dsm[];
    const uint32_t smb = s2u(dsm);
    const int tid = threadIdx.x;
    const int wid = tid >> 5;
    const int lane = tid & 31;
    const int wm = (wid & 3) * 32;
    const int wn = (wid >> 2) * 64;
    const int i0 = blockIdx.x * 128;
    const int tbase = blockIdx.y * TILES_PER;
    const int tgt = (blockIdx.y < JSPLIT / 2) ? 0 : 1;

    const uint32_t aoff = (uint32_t)(lane & 15) * TSTRIDE + (uint32_t)(lane >> 4) * 16;
    const uint32_t boff = (uint32_t)(((lane >> 3) & 1) * 8 + (lane & 7)) * TSTRIDE
                        + (uint32_t)(lane >> 4) * 16;

    load_tile(smb + OFF_A, g_Abf, i0, tid);
    load_tile(smb + OFF_B, g_Bbf, tbase * 128, tid);
    CP_COMMIT();
    load_tile(smb + OFF_B + TILE_BYTES, g_Bbf, (tbase + 1) * 128, tid);
    CP_COMMIT();

    float rsum[2][2] = {{0, 0}, {0, 0}};

    for (int t = 0; t < TILES_PER; ++t) {
        const int buf = t & 1;
        asm volatile("cp.async.wait_group 1;");
        __syncthreads();

        const uint32_t bb = smb + OFF_B + buf * TILE_BYTES;

        float acc[2][8][4];
#pragma unroll
        for (int f = 0; f < 2; ++f)
#pragma unroll
            for (int n = 0; n < 8; ++n)
#pragma unroll
                for (int r = 0; r < 4; ++r) acc[f][n][r] = 0.0f;

#pragma unroll
        for (int ks = 0; ks < 8; ++ks) {
            uint32_t ah[2][4];
#pragma unroll
            for (int f = 0; f < 2; ++f)
                ldsm4(ah[f], smb + OFF_A + (wm + f * 16) * TSTRIDE + ks * 32 + aoff);
#pragma unroll
            for (int g = 0; g < 4; ++g) {
                uint32_t bh[4];
                ldsm4(bh, bb + (wn + g * 16) * TSTRIDE + ks * 32 + boff);
#pragma unroll
                for (int f = 0; f < 2; ++f) {
                    mma_bf16(acc[f][2 * g], ah[f], bh[0], bh[2]);
                    mma_bf16(acc[f][2 * g + 1], ah[f], bh[1], bh[3]);
                }
            }
        }

        __syncthreads();
        if (t + 2 < TILES_PER)
            load_tile(smb + OFF_B + buf * TILE_BYTES, g_Bbf, (tbase + t + 2) * 128, tid);
        CP_COMMIT();

#pragma unroll
        for (int f = 0; f < 2; ++f) {
            float e0 = 0.0f, e1 = 0.0f;
#pragma unroll
            for (int n = 0; n < 8; ++n) {
                e0 += __expf(acc[f][n][0] * INV_TAU) + __expf(acc[f][n][1] * INV_TAU);
                e1 += __expf(acc[f][n][2] * INV_TAU) + __expf(acc[f][n][3] * INV_TAU);
            }
            rsum[f][0] += e0;
            rsum[f][1] += e1;
        }
    }

#pragma unroll
    for (int f = 0; f < 2; ++f)
#pragma unroll
        for (int r = 0; r < 2; ++r) {
            float v = rsum[f][r];
            v += __shfl_xor_sync(0xffffffffu, v, 1);
            v += __shfl_xor_sync(0xffffffffu, v, 2);
            if ((lane & 3) == 0) {
                int row = i0 + wm + f * 16 + (lane >> 2) + r * 8;
                atomicAdd(&g_sumall[tgt][row], v);
            }
        }
}

// ---------------- K4: MLP + softmax ----------------
#define MLP_ROWS 64
__global__ __launch_bounds__(256) void k_mlp(const float* __restrict__ W1,
                                             const float* __restrict__ b1,
                                             const float* __restrict__ W2,
                                             const float* __restrict__ b2,
                                             float* __restrict__ out_weights) {
    extern __shared__ float smf[];
    float* W1s = smf;
    float* feats = smf + 256 * 128;
    __shared__ float srow[2][2];

    int i0 = blockIdx.x * MLP_ROWS;
    int tid = threadIdx.x;

#pragma unroll 8
    for (int p = 0; p < 128; ++p) W1s[tid + p * 256] = W1[tid + p * 256];
#pragma unroll 4
    for (int p = 0; p < MLP_ROWS; ++p) {
        int s = tid + p * 256;
        int r = s >> 8, k = s & 255;
        feats[s] = (k < 128) ? g_repr[0][(size_t)(i0 + r) * D + k]
                             : g_repr[1][(size_t)(i0 + r) * D + (k - 128)];
    }
    __syncthreads();

    int c = tid & 127, half = tid >> 7;
    int lane = tid & 31;
    float b1c = b1[c], w20 = W2[2 * c], w21 = W2[2 * c + 1];

    for (int rp = 0; rp < MLP_ROWS / 2; ++rp) {
        const float* fr = feats + (rp * 2 + half) * 256;
        float h0 = 0, h1 = 0, h2 = 0, h3 = 0;
#pragma unroll 8
        for (int k = 0; k < 256; k += 4) {
            h0 = fmaf(fr[k + 0], W1s[(k + 0) * 128 + c], h0);
            h1 = fmaf(fr[k + 1], W1s[(k + 1) * 128 + c], h1);
            h2 = fmaf(fr[k + 2], W1s[(k + 2) * 128 + c], h2);
            h3 = fmaf(fr[k + 3], W1s[(k + 3) * 128 + c], h3);
        }
        float h = fmaxf((h0 + h1) + (h2 + h3) + b1c, 0.0f);
        float p0 = h * w20, p1 = h * w21;
#pragma unroll
        for (int o = 16; o; o >>= 1) {
            p0 += __shfl_xor_sync(0xffffffffu, p0, o);
            p1 += __shfl_xor_sync(0xffffffffu, p1, o);
        }
        if (tid < 4) srow[tid >> 1][tid & 1] = 0.0f;
        __syncthreads();
        if (lane == 0) {
            atomicAdd(&srow[half][0], p0);
            atomicAdd(&srow[half][1], p1);
        }
        __syncthreads();
        if (tid < 2) {
            int row = i0 + rp * 2 + tid;
            float o0 = srow[tid][0] + b2[0];
            float o1 = srow[tid][1] + b2[1];
            float mx = fmaxf(o0, o1);
            float e0 = expf(o0 - mx), e1 = expf(o1 - mx);
            float inv = 1.0f / (e0 + e1);
            float w0 = e0 * inv, w1 = e1 * inv;
            g_weights[2 * row] = w0;
            g_weights[2 * row + 1] = w1;
            out_weights[2 * row] = w0;
            out_weights[2 * row + 1] = w1;
        }
        __syncthreads();
    }
}

// ---------------- K5: loss ----------------
__global__ __launch_bounds__(256) void k_loss() {
    int idx = blockIdx.x * blockDim.x + threadIdx.x;
    int stride = gridDim.x * blockDim.x;
    float term = 0.0f;
    for (int i = idx; i < N; i += stride) {
        float w0 = g_weights[2 * i], w1 = g_weights[2 * i + 1];
        float pm = g_pos[0][i], pp = g_pos[1][i];
        float sm = g_sumall[0][i], sp = g_sumall[1][i];
        float wp = w0 * pm + w1 * pp;
        float wn = w0 * (sm - pm) + w1 * (sp - pp);
        float nei = fmaxf(g_rowsum[0][i] + g_rowsum[1][i], 1.0f);
        float ratio = wp / (wp + wn) / nei;
        ratio = fmaxf(ratio, 1e-10f);
        term += -logf(ratio);
    }
    __shared__ float red[256];
    red[threadIdx.x] = term;
    __syncthreads();
#pragma unroll
    for (int s = 128; s > 0; s >>= 1) {
        if (threadIdx.x < s) red[threadIdx.x] += red[threadIdx.x + s];
        __syncthreads();
    }
    if (threadIdx.x == 0) atomicAdd(&g_loss_acc, red[0]);
}

__global__ void k_finalize(float* __restrict__ out) {
    out[0] = g_loss_acc / (float)N;
}

// ---------------- launch (fork-join overlap) ----------------
extern "C" void kernel_launch(void* const* d_in, const int* in_sizes, int n_in,
                              void* d_out, int out_size) {
    const float* embF = (const float*)d_in[0];
    const float* embM = (const float*)d_in[1];
    const float* embP = (const float*)d_in[2];
    const float* FM_adj = (const float*)d_in[3];
    const float* FP_adj = (const float*)d_in[4];
    const float* W1 = (const float*)d_in[5];
    const float* b1 = (const float*)d_in[6];
    const float* W2 = (const float*)d_in[7];
    const float* b2 = (const float*)d_in[8];
    float* out = (float*)d_out;

    static cudaStream_t s1 = nullptr;
    static cudaEvent_t evA = nullptr, evB = nullptr;
    static bool attr_set = false;
    const int mlp_smem = (256 * 128 + MLP_ROWS * 256) * (int)sizeof(float);
    if (!attr_set) {
        cudaStreamCreateWithFlags(&s1, cudaStreamNonBlocking);
        cudaEventCreateWithFlags(&evA, cudaEventDisableTiming);
        cudaEventCreateWithFlags(&evB, cudaEventDisableTiming);
        cudaFuncSetAttribute(k_simsum_mma, cudaFuncAttributeMaxDynamicSharedMemorySize, SIMTC_SMEM);
        cudaFuncSetAttribute(k_mlp, cudaFuncAttributeMaxDynamicSharedMemorySize, mlp_smem);
        attr_set = true;
    }

    k_zero<<<(2 * N + 255) / 256, 256>>>();
    k_normalize<<<dim3(N, 3), 128>>>(embF, embM, embP);
    cudaEventRecord(evA, 0);

    // side branch: adjacency scan + MLP (DRAM-bound)
    cudaStreamWaitEvent(s1, evA, 0);
    k_repr_pos<<<dim3(N, 2), 128, 0, s1>>>(FM_adj, FP_adj, embM, embP);
    k_mlp<<<N / MLP_ROWS, 256, mlp_smem, s1>>>(W1, b1, W2, b2, out + 1);
    cudaEventRecord(evB, s1);

    // main branch: tensor-core sim sums
    k_simsum_mma<<<dim3(N / 128, JSPLIT), 256, SIMTC_SMEM>>>();

    cudaStreamWaitEvent(0, evB, 0);
    k_loss<<<24, 256>>>();
    k_finalize<<<1, 1>>>(out);
}

// round 7
// speedup vs baseline: 3.5003x; 1.1992x over previous
#include <cuda_runtime.h>
#include <cuda_bf16.h>
#include <math.h>
#include <stdint.h>

#define N 6144
#define D 128
#define INV_TAU 10.0f
#define NB (2 * N)
#define JSPLIT 6
#define TILES_PER 16   // 6*16*128 = 12288

// ---------------- device scratch ----------------
__device__ float g_Fn[N * D];
__device__ float g_Mn[N * D];
__device__ float g_Pn[N * D];
__device__ __nv_bfloat16 g_Abf[N * D];
__device__ __nv_bfloat16 g_Bbf[NB * D];
__device__ float g_repr[2][N * D];
__device__ float g_rowsum[2][N];
__device__ float g_pos[2][N];
__device__ float g_sumall[2][N];
__device__ float g_weights[N * 2];
__device__ float g_loss_acc;

// ---------------- PTX helpers ----------------
__device__ __forceinline__ uint32_t s2u(const void* p) {
    uint32_t a;
    asm("{ .reg .u64 t; cvta.to.shared.u64 t, %1; cvt.u32.u64 %0, t; }" : "=r"(a) : "l"(p));
    return a;
}
__device__ __forceinline__ void cp16(uint32_t dst, const void* src) {
    asm volatile("cp.async.cg.shared.global [%0], [%1], 16;" :: "r"(dst), "l"(src));
}
#define CP_COMMIT() asm volatile("cp.async.commit_group;")
__device__ __forceinline__ void ldsm4(uint32_t* r, uint32_t addr) {
    asm volatile("ldmatrix.sync.aligned.m8n8.x4.shared.b16 {%0,%1,%2,%3}, [%4];"
                 : "=r"(r[0]), "=r"(r[1]), "=r"(r[2]), "=r"(r[3]) : "r"(addr));
}
__device__ __forceinline__ void mma_bf16(float* d, const uint32_t* a, uint32_t b0, uint32_t b1) {
    asm volatile(
        "mma.sync.aligned.m16n8k16.row.col.f32.bf16.bf16.f32 "
        "{%0,%1,%2,%3}, {%4,%5,%6,%7}, {%8,%9}, {%0,%1,%2,%3};"
        : "+f"(d[0]), "+f"(d[1]), "+f"(d[2]), "+f"(d[3])
        : "r"(a[0]), "r"(a[1]), "r"(a[2]), "r"(a[3]), "r"(b0), "r"(b1));
}

// SMEM tile: 128 rows x 136 bf16 (stride 272 B, +8 pad -> conflict-free ldmatrix)
#define TSTRIDE 272
#define TILE_BYTES (128 * TSTRIDE)
static constexpr int OFF_A = 0;
static constexpr int OFF_B = TILE_BYTES;
static constexpr int SIMTC_SMEM = 3 * TILE_BYTES;  // 104448

// ---------------- K0: zero ----------------
__global__ void k_zero() {
    int idx = blockIdx.x * blockDim.x + threadIdx.x;
    if (idx < 2 * N) g_sumall[idx / N][idx % N] = 0.0f;
    if (idx == 0) g_loss_acc = 0.0f;
}

// ---------------- K1: normalize + bf16 cast ----------------
__global__ void k_normalize(const float* __restrict__ embF,
                            const float* __restrict__ embM,
                            const float* __restrict__ embP) {
    int i = blockIdx.x;
    int which = blockIdx.y;
    const float* src = (which == 0) ? embF : (which == 1) ? embM : embP;
    float* dst = (which == 0) ? g_Fn : (which == 1) ? g_Mn : g_Pn;
    int t = threadIdx.x;  // 128
    float v = src[(size_t)i * D + t];
    __shared__ float red[128];
    red[t] = v * v;
    __syncthreads();
#pragma unroll
    for (int s = 64; s > 0; s >>= 1) {
        if (t < s) red[t] += red[t + s];
        __syncthreads();
    }
    float norm = fmaxf(sqrtf(red[0]), 1e-12f);
    float nv = v / norm;
    dst[(size_t)i * D + t] = nv;
    __nv_bfloat16 h = __float2bfloat16(nv);
    if (which == 0) g_Abf[i * D + t] = h;
    else g_Bbf[((which == 1) ? i : (N + i)) * D + t] = h;
}

// ---------------- K2: adjacency scan (warp-scan compaction) ----------------
#define MAXNZ 768
#define VPT 12  // (N/4)/128 float4 per thread
__global__ __launch_bounds__(128) void k_repr_pos(
    const float* __restrict__ FM_adj, const float* __restrict__ FP_adj,
    const float* __restrict__ embM, const float* __restrict__ embP) {
    int i = blockIdx.x;
    int w = blockIdx.y;
    const float* adj = (w == 0) ? FM_adj : FP_adj;
    const float* emb = (w == 0) ? embM : embP;
    const float* nrm = (w == 0) ? g_Mn : g_Pn;
    int t = threadIdx.x;
    int lane = t & 31;

    __shared__ int s_idx[MAXNZ];
    __shared__ float s_val[MAXNZ];
    __shared__ int s_cnt;
    __shared__ float s_rowsum;
    __shared__ float s_pos;
    __shared__ float s_F[D];

    if (t == 0) { s_cnt = 0; s_rowsum = 0.0f; s_pos = 0.0f; }
    s_F[t] = g_Fn[(size_t)i * D + t];

    const float4* arow = (const float4*)(adj + (size_t)i * N);
    float4 v[VPT];
#pragma unroll
    for (int q = 0; q < VPT; ++q) v[q] = __ldcs(&arow[t + q * 128]);
    __syncthreads();  // s_cnt/s_rowsum/s_pos init must be visible before atomics

    // pass 1: local nonzero count + local sum
    int nloc = 0;
    float myrs = 0.0f;
#pragma unroll
    for (int q = 0; q < VPT; ++q) {
        float comp[4] = {v[q].x, v[q].y, v[q].z, v[q].w};
#pragma unroll
        for (int e = 0; e < 4; ++e) {
            if (comp[e] != 0.0f) { ++nloc; myrs += comp[e]; }
        }
    }
    // warp inclusive scan of counts -> one atomic per warp
    int inc = nloc;
#pragma unroll
    for (int o = 1; o < 32; o <<= 1) {
        int u = __shfl_up_sync(0xffffffffu, inc, o);
        if (lane >= o) inc += u;
    }
    int wtot = __shfl_sync(0xffffffffu, inc, 31);
    int base = 0;
    if (lane == 31) base = atomicAdd(&s_cnt, wtot);
    base = __shfl_sync(0xffffffffu, base, 31);
    int p = base + inc - nloc;
    // pass 2: direct writes
#pragma unroll
    for (int q = 0; q < VPT; ++q) {
        int c = t + q * 128;
        float comp[4] = {v[q].x, v[q].y, v[q].z, v[q].w};
#pragma unroll
        for (int e = 0; e < 4; ++e) {
            float x = comp[e];
            if (x != 0.0f) {
                if (p < MAXNZ) { s_idx[p] = c * 4 + e; s_val[p] = x; }
                ++p;
            }
        }
    }
#pragma unroll
    for (int o = 16; o; o >>= 1) myrs += __shfl_xor_sync(0xffffffffu, myrs, o);
    if (lane == 0) atomicAdd(&s_rowsum, myrs);
    __syncthreads();

    int cnt = min(s_cnt, MAXNZ);
    float rs = s_rowsum;
    float denom = fmaxf(rs, 1.0f);

    // repr gather: 4 independent accumulator chains
    float a0 = 0, a1 = 0, a2 = 0, a3 = 0;
    int e = 0;
    for (; e + 4 <= cnt; e += 4) {
        a0 += s_val[e + 0] * emb[(size_t)s_idx[e + 0] * D + t];
        a1 += s_val[e + 1] * emb[(size_t)s_idx[e + 1] * D + t];
        a2 += s_val[e + 2] * emb[(size_t)s_idx[e + 2] * D + t];
        a3 += s_val[e + 3] * emb[(size_t)s_idx[e + 3] * D + t];
    }
    for (; e < cnt; ++e) a0 += s_val[e] * emb[(size_t)s_idx[e] * D + t];
    g_repr[w][(size_t)i * D + t] = ((a0 + a1) + (a2 + a3)) / denom;
    if (t == 0) g_rowsum[w][i] = rs;

    int warp = t >> 5;
    float lp = 0.0f;
    for (int q = warp; q < cnt; q += 4) {
        int j = s_idx[q];
        const float* nr = nrm + (size_t)j * D;
        float pd = s_F[lane] * nr[lane]
                 + s_F[lane + 32] * nr[lane + 32]
                 + s_F[lane + 64] * nr[lane + 64]
                 + s_F[lane + 96] * nr[lane + 96];
#pragma unroll
        for (int o = 16; o; o >>= 1) pd += __shfl_xor_sync(0xffffffffu, pd, o);
        if (lane == 0) lp += s_val[q] * __expf(pd * INV_TAU);
    }
    if (lane == 0) atomicAdd(&s_pos, lp);
    __syncthreads();
    if (t == 0) g_pos[w][i] = s_pos;
}

// ---------------- K3: single-pass bf16 HMMA sim row sums ----------------
__device__ __forceinline__ void load_tile(uint32_t dst, const __nv_bfloat16* src,
                                          int row0, int tid) {
#pragma unroll
    for (int p = 0; p < 8; ++p) {
        int idx = tid + (p << 8);
        int r = idx >> 4, c = idx & 15;
        cp16(dst + r * TSTRIDE + c * 16, src + (size_t)(row0 + r) * D + c * 8);
    }
}

__global__ __launch_bounds__(256, 2) void k_simsum_mma() {
    extern __shared__ __align__(16) char dsm[];
    const uint32_t smb = s2u(dsm);
    const int tid = threadIdx.x;
    const int wid = tid >> 5;
    const int lane = tid & 31;
    const int wm = (wid & 3) * 32;
    const int wn = (wid >> 2) * 64;
    const int i0 = blockIdx.x * 128;
    const int tbase = blockIdx.y * TILES_PER;
    const int tgt = (blockIdx.y < JSPLIT / 2) ? 0 : 1;

    const uint32_t aoff = (uint32_t)(lane & 15) * TSTRIDE + (uint32_t)(lane >> 4) * 16;
    const uint32_t boff = (uint32_t)(((lane >> 3) & 1) * 8 + (lane & 7)) * TSTRIDE
                        + (uint32_t)(lane >> 4) * 16;

    load_tile(smb + OFF_A, g_Abf, i0, tid);
    load_tile(smb + OFF_B, g_Bbf, tbase * 128, tid);
    CP_COMMIT();
    load_tile(smb + OFF_B + TILE_BYTES, g_Bbf, (tbase + 1) * 128, tid);
    CP_COMMIT();

    float rsum[2][2] = {{0, 0}, {0, 0}};

    for (int t = 0; t < TILES_PER; ++t) {
        const int buf = t & 1;
        asm volatile("cp.async.wait_group 1;");
        __syncthreads();

        const uint32_t bb = smb + OFF_B + buf * TILE_BYTES;

        float acc[2][8][4];
#pragma unroll
        for (int f = 0; f < 2; ++f)
#pragma unroll
            for (int n = 0; n < 8; ++n)
#pragma unroll
                for (int r = 0; r < 4; ++r) acc[f][n][r] = 0.0f;

#pragma unroll
        for (int ks = 0; ks < 8; ++ks) {
            uint32_t ah[2][4];
#pragma unroll
            for (int f = 0; f < 2; ++f)
                ldsm4(ah[f], smb + OFF_A + (wm + f * 16) * TSTRIDE + ks * 32 + aoff);
#pragma unroll
            for (int g = 0; g < 4; ++g) {
                uint32_t bh[4];
                ldsm4(bh, bb + (wn + g * 16) * TSTRIDE + ks * 32 + boff);
#pragma unroll
                for (int f = 0; f < 2; ++f) {
                    mma_bf16(acc[f][2 * g], ah[f], bh[0], bh[2]);
                    mma_bf16(acc[f][2 * g + 1], ah[f], bh[1], bh[3]);
                }
            }
        }

        __syncthreads();
        if (t + 2 < TILES_PER)
            load_tile(smb + OFF_B + buf * TILE_BYTES, g_Bbf, (tbase + t + 2) * 128, tid);
        CP_COMMIT();

#pragma unroll
        for (int f = 0; f < 2; ++f) {
            float e0 = 0.0f, e1 = 0.0f;
#pragma unroll
            for (int n = 0; n < 8; ++n) {
                e0 += __expf(acc[f][n][0] * INV_TAU) + __expf(acc[f][n][1] * INV_TAU);
                e1 += __expf(acc[f][n][2] * INV_TAU) + __expf(acc[f][n][3] * INV_TAU);
            }
            rsum[f][0] += e0;
            rsum[f][1] += e1;
        }
    }

#pragma unroll
    for (int f = 0; f < 2; ++f)
#pragma unroll
        for (int r = 0; r < 2; ++r) {
            float v = rsum[f][r];
            v += __shfl_xor_sync(0xffffffffu, v, 1);
            v += __shfl_xor_sync(0xffffffffu, v, 2);
            if ((lane & 3) == 0) {
                int row = i0 + wm + f * 16 + (lane >> 2) + r * 8;
                atomicAdd(&g_sumall[tgt][row], v);
            }
        }
}

// ---------------- K4: MLP + softmax (warp-owned rows, no block syncs in loop) ----
#define MLP_ROWS 48
#define FSTR 257
#define MLP_SMEM ((256 * 128 + MLP_ROWS * FSTR) * (int)sizeof(float))
__global__ __launch_bounds__(256) void k_mlp(const float* __restrict__ W1,
                                             const float* __restrict__ b1,
                                             const float* __restrict__ W2,
                                             const float* __restrict__ b2,
                                             float* __restrict__ out_weights) {
    extern __shared__ float smf[];
    float* W1s = smf;                    // [256][128] native layout
    float* feats = smf + 256 * 128;      // [48][FSTR]

    const int tid = threadIdx.x;
    const int lane = tid & 31;
    const int wp = tid >> 5;
    const int i0 = blockIdx.x * MLP_ROWS;

    // stage W1 (32768 floats = 8192 float4)
#pragma unroll
    for (int p = 0; p < 32; ++p) {
        int s = tid + p * 256;
        ((float4*)W1s)[s] = ((const float4*)W1)[s];
    }
    // stage feats [48][256]
#pragma unroll
    for (int p = 0; p < MLP_ROWS; ++p) {
        int s = tid + p * 256;
        int r = s >> 8, k = s & 255;
        feats[r * FSTR + k] = (k < 128) ? g_repr[0][(size_t)(i0 + r) * D + k]
                                        : g_repr[1][(size_t)(i0 + r) * D + (k - 128)];
    }
    __syncthreads();

    // thread owns 4 consecutive cols (c = 4*lane) for 6 rows (warp-owned)
    const int c4 = lane;
    const float4 b1v = ((const float4*)b1)[c4];
    const float4 w2a = ((const float4*)W2)[2 * c4];
    const float4 w2b = ((const float4*)W2)[2 * c4 + 1];
    const int r0 = wp * 6;  // 8 warps * 6 rows = 48

    float acc[6][4];
#pragma unroll
    for (int r = 0; r < 6; ++r)
#pragma unroll
        for (int q = 0; q < 4; ++q) acc[r][q] = 0.0f;

#pragma unroll 4
    for (int k = 0; k < 256; ++k) {
        float4 wv = *(const float4*)&W1s[k * 128 + 4 * c4];
#pragma unroll
        for (int r = 0; r < 6; ++r) {
            float f = feats[(r0 + r) * FSTR + k];
            acc[r][0] = fmaf(f, wv.x, acc[r][0]);
            acc[r][1] = fmaf(f, wv.y, acc[r][1]);
            acc[r][2] = fmaf(f, wv.z, acc[r][2]);
            acc[r][3] = fmaf(f, wv.w, acc[r][3]);
        }
    }

#pragma unroll
    for (int r = 0; r < 6; ++r) {
        float h0 = fmaxf(acc[r][0] + b1v.x, 0.0f);
        float h1 = fmaxf(acc[r][1] + b1v.y, 0.0f);
        float h2 = fmaxf(acc[r][2] + b1v.z, 0.0f);
        float h3 = fmaxf(acc[r][3] + b1v.w, 0.0f);
        float p0 = h0 * w2a.x + h1 * w2a.z + h2 * w2b.x + h3 * w2b.z;
        float p1 = h0 * w2a.y + h1 * w2a.w + h2 * w2b.y + h3 * w2b.w;
#pragma unroll
        for (int o = 16; o; o >>= 1) {
            p0 += __shfl_xor_sync(0xffffffffu, p0, o);
            p1 += __shfl_xor_sync(0xffffffffu, p1, o);
        }
        if (lane == 0) {
            int row = i0 + r0 + r;
            float o0 = p0 + b2[0];
            float o1 = p1 + b2[1];
            float mx = fmaxf(o0, o1);
            float e0 = expf(o0 - mx), e1 = expf(o1 - mx);
            float inv = 1.0f / (e0 + e1);
            float w0 = e0 * inv, w1 = e1 * inv;
            g_weights[2 * row] = w0;
            g_weights[2 * row + 1] = w1;
            out_weights[2 * row] = w0;
            out_weights[2 * row + 1] = w1;
        }
    }
}

// ---------------- K5: loss ----------------
__global__ __launch_bounds__(256) void k_loss() {
    int idx = blockIdx.x * blockDim.x + threadIdx.x;
    int stride = gridDim.x * blockDim.x;
    float term = 0.0f;
    for (int i = idx; i < N; i += stride) {
        float w0 = g_weights[2 * i], w1 = g_weights[2 * i + 1];
        float pm = g_pos[0][i], pp = g_pos[1][i];
        float sm = g_sumall[0][i], sp = g_sumall[1][i];
        float wpv = w0 * pm + w1 * pp;
        float wn = w0 * (sm - pm) + w1 * (sp - pp);
        float nei = fmaxf(g_rowsum[0][i] + g_rowsum[1][i], 1.0f);
        float ratio = wpv / (wpv + wn) / nei;
        ratio = fmaxf(ratio, 1e-10f);
        term += -logf(ratio);
    }
    __shared__ float red[256];
    red[threadIdx.x] = term;
    __syncthreads();
#pragma unroll
    for (int s = 128; s > 0; s >>= 1) {
        if (threadIdx.x < s) red[threadIdx.x] += red[threadIdx.x + s];
        __syncthreads();
    }
    if (threadIdx.x == 0) atomicAdd(&g_loss_acc, red[0]);
}

__global__ void k_finalize(float* __restrict__ out) {
    out[0] = g_loss_acc / (float)N;
}

// ---------------- launch (fork-join overlap) ----------------
extern "C" void kernel_launch(void* const* d_in, const int* in_sizes, int n_in,
                              void* d_out, int out_size) {
    const float* embF = (const float*)d_in[0];
    const float* embM = (const float*)d_in[1];
    const float* embP = (const float*)d_in[2];
    const float* FM_adj = (const float*)d_in[3];
    const float* FP_adj = (const float*)d_in[4];
    const float* W1 = (const float*)d_in[5];
    const float* b1 = (const float*)d_in[6];
    const float* W2 = (const float*)d_in[7];
    const float* b2 = (const float*)d_in[8];
    float* out = (float*)d_out;

    static cudaStream_t s1 = nullptr;
    static cudaEvent_t evA = nullptr, evB = nullptr;
    static bool attr_set = false;
    if (!attr_set) {
        cudaStreamCreateWithFlags(&s1, cudaStreamNonBlocking);
        cudaEventCreateWithFlags(&evA, cudaEventDisableTiming);
        cudaEventCreateWithFlags(&evB, cudaEventDisableTiming);
        cudaFuncSetAttribute(k_simsum_mma, cudaFuncAttributeMaxDynamicSharedMemorySize, SIMTC_SMEM);
        cudaFuncSetAttribute(k_mlp, cudaFuncAttributeMaxDynamicSharedMemorySize, MLP_SMEM);
        attr_set = true;
    }

    k_zero<<<(2 * N + 255) / 256, 256>>>();
    k_normalize<<<dim3(N, 3), 128>>>(embF, embM, embP);
    cudaEventRecord(evA, 0);

    // side branch: adjacency scan + MLP (DRAM/latency-bound)
    cudaStreamWaitEvent(s1, evA, 0);
    k_repr_pos<<<dim3(N, 2), 128, 0, s1>>>(FM_adj, FP_adj, embM, embP);
    k_mlp<<<N / MLP_ROWS, 256, MLP_SMEM, s1>>>(W1, b1, W2, b2, out + 1);
    cudaEventRecord(evB, s1);

    // main branch: tensor-core sim sums
    k_simsum_mma<<<dim3(N / 128, JSPLIT), 256, SIMTC_SMEM>>>();

    cudaStreamWaitEvent(0, evB, 0);
    k_loss<<<24, 256>>>();
    k_finalize<<<1, 1>>>(out);
}

// round 8
// speedup vs baseline: 3.6108x; 1.0316x over previous
#include <cuda_runtime.h>
#include <cuda_bf16.h>
#include <math.h>
#include <stdint.h>

#define N 6144
#define D 128
#define INV_TAU 10.0f
#define NB (2 * N)
#define JSPLIT 12
#define TILES_PER 16   // 12*16*64 = 12288 columns

// ---------------- device scratch ----------------
__device__ float g_Fn[N * D];
__device__ float g_Mn[N * D];
__device__ float g_Pn[N * D];
__device__ __nv_bfloat16 g_Abf[N * D];
__device__ __nv_bfloat16 g_Bbf[NB * D];
__device__ float g_repr[2][N * D];
__device__ float g_rowsum[2][N];
__device__ float g_pos[2][N];
__device__ float g_sumall[2][N];
__device__ float g_weights[N * 2];
__device__ float g_loss_acc;

// ---------------- PTX helpers ----------------
__device__ __forceinline__ uint32_t s2u(const void* p) {
    uint32_t a;
    asm("{ .reg .u64 t; cvta.to.shared.u64 t, %1; cvt.u32.u64 %0, t; }" : "=r"(a) : "l"(p));
    return a;
}
__device__ __forceinline__ void cp16(uint32_t dst, const void* src) {
    asm volatile("cp.async.cg.shared.global [%0], [%1], 16;" :: "r"(dst), "l"(src));
}
#define CP_COMMIT() asm volatile("cp.async.commit_group;")
__device__ __forceinline__ void ldsm4(uint32_t* r, uint32_t addr) {
    asm volatile("ldmatrix.sync.aligned.m8n8.x4.shared.b16 {%0,%1,%2,%3}, [%4];"
                 : "=r"(r[0]), "=r"(r[1]), "=r"(r[2]), "=r"(r[3]) : "r"(addr));
}
__device__ __forceinline__ void mma_bf16(float* d, const uint32_t* a, uint32_t b0, uint32_t b1) {
    asm volatile(
        "mma.sync.aligned.m16n8k16.row.col.f32.bf16.bf16.f32 "
        "{%0,%1,%2,%3}, {%4,%5,%6,%7}, {%8,%9}, {%0,%1,%2,%3};"
        : "+f"(d[0]), "+f"(d[1]), "+f"(d[2]), "+f"(d[3])
        : "r"(a[0]), "r"(a[1]), "r"(a[2]), "r"(a[3]), "r"(b0), "r"(b1));
}

// SMEM tiles (stride 272 B = 128 data + 16 pad -> conflict-free ldmatrix)
#define TSTRIDE 272
#define A_TILE_BYTES (128 * TSTRIDE)   // 34816
#define B_TILE_BYTES (64 * TSTRIDE)    // 17408
static constexpr int OFF_A = 0;
static constexpr int OFF_B = A_TILE_BYTES;
static constexpr int SIMTC_SMEM = A_TILE_BYTES + 2 * B_TILE_BYTES;  // 69632

// ---------------- K0: zero ----------------
__global__ void k_zero() {
    int idx = blockIdx.x * blockDim.x + threadIdx.x;
    if (idx < 2 * N) g_sumall[idx / N][idx % N] = 0.0f;
    if (idx == 0) g_loss_acc = 0.0f;
}

// ---------------- K1: normalize + bf16 cast ----------------
__global__ void k_normalize(const float* __restrict__ embF,
                            const float* __restrict__ embM,
                            const float* __restrict__ embP) {
    int i = blockIdx.x;
    int which = blockIdx.y;
    const float* src = (which == 0) ? embF : (which == 1) ? embM : embP;
    float* dst = (which == 0) ? g_Fn : (which == 1) ? g_Mn : g_Pn;
    int t = threadIdx.x;  // 128
    float v = src[(size_t)i * D + t];
    __shared__ float red[128];
    red[t] = v * v;
    __syncthreads();
#pragma unroll
    for (int s = 64; s > 0; s >>= 1) {
        if (t < s) red[t] += red[t + s];
        __syncthreads();
    }
    float norm = fmaxf(sqrtf(red[0]), 1e-12f);
    float nv = v / norm;
    dst[(size_t)i * D + t] = nv;
    __nv_bfloat16 h = __float2bfloat16(nv);
    if (which == 0) g_Abf[i * D + t] = h;
    else g_Bbf[((which == 1) ? i : (N + i)) * D + t] = h;
}

// ---------------- K2: adjacency scan (warp-scan compaction) ----------------
#define MAXNZ 768
#define VPT 12  // (N/4)/128 float4 per thread
__global__ __launch_bounds__(128) void k_repr_pos(
    const float* __restrict__ FM_adj, const float* __restrict__ FP_adj,
    const float* __restrict__ embM, const float* __restrict__ embP) {
    int i = blockIdx.x;
    int w = blockIdx.y;
    const float* adj = (w == 0) ? FM_adj : FP_adj;
    const float* emb = (w == 0) ? embM : embP;
    const float* nrm = (w == 0) ? g_Mn : g_Pn;
    int t = threadIdx.x;
    int lane = t & 31;

    __shared__ int s_idx[MAXNZ];
    __shared__ float s_val[MAXNZ];
    __shared__ int s_cnt;
    __shared__ float s_rowsum;
    __shared__ float s_pos;
    __shared__ float s_F[D];

    if (t == 0) { s_cnt = 0; s_rowsum = 0.0f; s_pos = 0.0f; }
    s_F[t] = g_Fn[(size_t)i * D + t];

    const float4* arow = (const float4*)(adj + (size_t)i * N);
    float4 v[VPT];
#pragma unroll
    for (int q = 0; q < VPT; ++q) v[q] = __ldcs(&arow[t + q * 128]);
    __syncthreads();  // init visible before atomics

    int nloc = 0;
    float myrs = 0.0f;
#pragma unroll
    for (int q = 0; q < VPT; ++q) {
        float comp[4] = {v[q].x, v[q].y, v[q].z, v[q].w};
#pragma unroll
        for (int e = 0; e < 4; ++e) {
            if (comp[e] != 0.0f) { ++nloc; myrs += comp[e]; }
        }
    }
    int inc = nloc;
#pragma unroll
    for (int o = 1; o < 32; o <<= 1) {
        int u = __shfl_up_sync(0xffffffffu, inc, o);
        if (lane >= o) inc += u;
    }
    int wtot = __shfl_sync(0xffffffffu, inc, 31);
    int base = 0;
    if (lane == 31) base = atomicAdd(&s_cnt, wtot);
    base = __shfl_sync(0xffffffffu, base, 31);
    int p = base + inc - nloc;
#pragma unroll
    for (int q = 0; q < VPT; ++q) {
        int c = t + q * 128;
        float comp[4] = {v[q].x, v[q].y, v[q].z, v[q].w};
#pragma unroll
        for (int e = 0; e < 4; ++e) {
            float x = comp[e];
            if (x != 0.0f) {
                if (p < MAXNZ) { s_idx[p] = c * 4 + e; s_val[p] = x; }
                ++p;
            }
        }
    }
#pragma unroll
    for (int o = 16; o; o >>= 1) myrs += __shfl_xor_sync(0xffffffffu, myrs, o);
    if (lane == 0) atomicAdd(&s_rowsum, myrs);
    __syncthreads();

    int cnt = min(s_cnt, MAXNZ);
    float rs = s_rowsum;
    float denom = fmaxf(rs, 1.0f);

    float a0 = 0, a1 = 0, a2 = 0, a3 = 0;
    int e = 0;
    for (; e + 4 <= cnt; e += 4) {
        a0 += s_val[e + 0] * emb[(size_t)s_idx[e + 0] * D + t];
        a1 += s_val[e + 1] * emb[(size_t)s_idx[e + 1] * D + t];
        a2 += s_val[e + 2] * emb[(size_t)s_idx[e + 2] * D + t];
        a3 += s_val[e + 3] * emb[(size_t)s_idx[e + 3] * D + t];
    }
    for (; e < cnt; ++e) a0 += s_val[e] * emb[(size_t)s_idx[e] * D + t];
    g_repr[w][(size_t)i * D + t] = ((a0 + a1) + (a2 + a3)) / denom;
    if (t == 0) g_rowsum[w][i] = rs;

    int warp = t >> 5;
    float lp = 0.0f;
    for (int q = warp; q < cnt; q += 4) {
        int j = s_idx[q];
        const float* nr = nrm + (size_t)j * D;
        float pd = s_F[lane] * nr[lane]
                 + s_F[lane + 32] * nr[lane + 32]
                 + s_F[lane + 64] * nr[lane + 64]
                 + s_F[lane + 96] * nr[lane + 96];
#pragma unroll
        for (int o = 16; o; o >>= 1) pd += __shfl_xor_sync(0xffffffffu, pd, o);
        if (lane == 0) lp += s_val[q] * __expf(pd * INV_TAU);
    }
    if (lane == 0) atomicAdd(&s_pos, lp);
    __syncthreads();
    if (t == 0) g_pos[w][i] = s_pos;
}

// ---------------- K3: bf16 HMMA sim row sums (BN=64, spill-free) ----------------
__device__ __forceinline__ void load_tileA(uint32_t dst, const __nv_bfloat16* src,
                                           int row0, int tid) {
#pragma unroll
    for (int p = 0; p < 8; ++p) {
        int idx = tid + (p << 8);
        int r = idx >> 4, c = idx & 15;
        cp16(dst + r * TSTRIDE + c * 16, src + (size_t)(row0 + r) * D + c * 8);
    }
}
__device__ __forceinline__ void load_tileB(uint32_t dst, const __nv_bfloat16* src,
                                           int row0, int tid) {
#pragma unroll
    for (int p = 0; p < 4; ++p) {
        int idx = tid + (p << 8);
        int r = idx >> 4, c = idx & 15;
        cp16(dst + r * TSTRIDE + c * 16, src + (size_t)(row0 + r) * D + c * 8);
    }
}

__global__ __launch_bounds__(256, 2) void k_simsum_mma() {
    extern __shared__ __align__(16) char dsm[];
    const uint32_t smb = s2u(dsm);
    const int tid = threadIdx.x;
    const int wid = tid >> 5;
    const int lane = tid & 31;
    const int wm = (wid & 3) * 32;    // warp m offset (4 warps over 128)
    const int wn = (wid >> 2) * 32;   // warp n offset (2 warps over 64)
    const int i0 = blockIdx.x * 128;
    const int tbase = blockIdx.y * TILES_PER;
    const int tgt = (blockIdx.y < JSPLIT / 2) ? 0 : 1;

    const uint32_t aoff = (uint32_t)(lane & 15) * TSTRIDE + (uint32_t)(lane >> 4) * 16;
    const uint32_t boff = (uint32_t)(((lane >> 3) & 1) * 8 + (lane & 7)) * TSTRIDE
                        + (uint32_t)(lane >> 4) * 16;

    load_tileA(smb + OFF_A, g_Abf, i0, tid);
    load_tileB(smb + OFF_B, g_Bbf, tbase * 64, tid);
    CP_COMMIT();
    load_tileB(smb + OFF_B + B_TILE_BYTES, g_Bbf, (tbase + 1) * 64, tid);
    CP_COMMIT();

    float rsum[2][2] = {{0, 0}, {0, 0}};

    for (int t = 0; t < TILES_PER; ++t) {
        const int buf = t & 1;
        asm volatile("cp.async.wait_group 1;");
        __syncthreads();

        const uint32_t bb = smb + OFF_B + buf * B_TILE_BYTES;

        float acc[2][4][4];
#pragma unroll
        for (int f = 0; f < 2; ++f)
#pragma unroll
            for (int n = 0; n < 4; ++n)
#pragma unroll
                for (int r = 0; r < 4; ++r) acc[f][n][r] = 0.0f;

#pragma unroll
        for (int ks = 0; ks < 8; ++ks) {
            uint32_t ah[2][4];
#pragma unroll
            for (int f = 0; f < 2; ++f)
                ldsm4(ah[f], smb + OFF_A + (wm + f * 16) * TSTRIDE + ks * 32 + aoff);
#pragma unroll
            for (int g = 0; g < 2; ++g) {
                uint32_t bh[4];
                ldsm4(bh, bb + (wn + g * 16) * TSTRIDE + ks * 32 + boff);
#pragma unroll
                for (int f = 0; f < 2; ++f) {
                    mma_bf16(acc[f][2 * g], ah[f], bh[0], bh[2]);
                    mma_bf16(acc[f][2 * g + 1], ah[f], bh[1], bh[3]);
                }
            }
        }

        __syncthreads();
        if (t + 2 < TILES_PER)
            load_tileB(smb + OFF_B + buf * B_TILE_BYTES, g_Bbf, (tbase + t + 2) * 64, tid);
        CP_COMMIT();

#pragma unroll
        for (int f = 0; f < 2; ++f) {
            float e0 = 0.0f, e1 = 0.0f;
#pragma unroll
            for (int n = 0; n < 4; ++n) {
                e0 += __expf(acc[f][n][0] * INV_TAU) + __expf(acc[f][n][1] * INV_TAU);
                e1 += __expf(acc[f][n][2] * INV_TAU) + __expf(acc[f][n][3] * INV_TAU);
            }
            rsum[f][0] += e0;
            rsum[f][1] += e1;
        }
    }

#pragma unroll
    for (int f = 0; f < 2; ++f)
#pragma unroll
        for (int r = 0; r < 2; ++r) {
            float v = rsum[f][r];
            v += __shfl_xor_sync(0xffffffffu, v, 1);
            v += __shfl_xor_sync(0xffffffffu, v, 2);
            if ((lane & 3) == 0) {
                int row = i0 + wm + f * 16 + (lane >> 2) + r * 8;
                atomicAdd(&g_sumall[tgt][row], v);
            }
        }
}

// ---------------- K4: MLP + softmax (warp-owned rows) ----------------
#define MLP_ROWS 48
#define FSTR 257
#define MLP_SMEM ((256 * 128 + MLP_ROWS * FSTR) * (int)sizeof(float))
__global__ __launch_bounds__(256) void k_mlp(const float* __restrict__ W1,
                                             const float* __restrict__ b1,
                                             const float* __restrict__ W2,
                                             const float* __restrict__ b2,
                                             float* __restrict__ out_weights) {
    extern __shared__ float smf[];
    float* W1s = smf;
    float* feats = smf + 256 * 128;

    const int tid = threadIdx.x;
    const int lane = tid & 31;
    const int wp = tid >> 5;
    const int i0 = blockIdx.x * MLP_ROWS;

#pragma unroll
    for (int p = 0; p < 32; ++p) {
        int s = tid + p * 256;
        ((float4*)W1s)[s] = ((const float4*)W1)[s];
    }
#pragma unroll
    for (int p = 0; p < MLP_ROWS; ++p) {
        int s = tid + p * 256;
        int r = s >> 8, k = s & 255;
        feats[r * FSTR + k] = (k < 128) ? g_repr[0][(size_t)(i0 + r) * D + k]
                                        : g_repr[1][(size_t)(i0 + r) * D + (k - 128)];
    }
    __syncthreads();

    const int c4 = lane;
    const float4 b1v = ((const float4*)b1)[c4];
    const float4 w2a = ((const float4*)W2)[2 * c4];
    const float4 w2b = ((const float4*)W2)[2 * c4 + 1];
    const int r0 = wp * 6;

    float acc[6][4];
#pragma unroll
    for (int r = 0; r < 6; ++r)
#pragma unroll
        for (int q = 0; q < 4; ++q) acc[r][q] = 0.0f;

#pragma unroll 4
    for (int k = 0; k < 256; ++k) {
        float4 wv = *(const float4*)&W1s[k * 128 + 4 * c4];
#pragma unroll
        for (int r = 0; r < 6; ++r) {
            float f = feats[(r0 + r) * FSTR + k];
            acc[r][0] = fmaf(f, wv.x, acc[r][0]);
            acc[r][1] = fmaf(f, wv.y, acc[r][1]);
            acc[r][2] = fmaf(f, wv.z, acc[r][2]);
            acc[r][3] = fmaf(f, wv.w, acc[r][3]);
        }
    }

#pragma unroll
    for (int r = 0; r < 6; ++r) {
        float h0 = fmaxf(acc[r][0] + b1v.x, 0.0f);
        float h1 = fmaxf(acc[r][1] + b1v.y, 0.0f);
        float h2 = fmaxf(acc[r][2] + b1v.z, 0.0f);
        float h3 = fmaxf(acc[r][3] + b1v.w, 0.0f);
        float p0 = h0 * w2a.x + h1 * w2a.z + h2 * w2b.x + h3 * w2b.z;
        float p1 = h0 * w2a.y + h1 * w2a.w + h2 * w2b.y + h3 * w2b.w;
#pragma unroll
        for (int o = 16; o; o >>= 1) {
            p0 += __shfl_xor_sync(0xffffffffu, p0, o);
            p1 += __shfl_xor_sync(0xffffffffu, p1, o);
        }
        if (lane == 0) {
            int row = i0 + r0 + r;
            float o0 = p0 + b2[0];
            float o1 = p1 + b2[1];
            float mx = fmaxf(o0, o1);
            float e0 = expf(o0 - mx), e1 = expf(o1 - mx);
            float inv = 1.0f / (e0 + e1);
            float w0 = e0 * inv, w1 = e1 * inv;
            g_weights[2 * row] = w0;
            g_weights[2 * row + 1] = w1;
            out_weights[2 * row] = w0;
            out_weights[2 * row + 1] = w1;
        }
    }
}

// ---------------- K5: loss ----------------
__global__ __launch_bounds__(256) void k_loss() {
    int idx = blockIdx.x * blockDim.x + threadIdx.x;
    int stride = gridDim.x * blockDim.x;
    float term = 0.0f;
    for (int i = idx; i < N; i += stride) {
        float w0 = g_weights[2 * i], w1 = g_weights[2 * i + 1];
        float pm = g_pos[0][i], pp = g_pos[1][i];
        float sm = g_sumall[0][i], sp = g_sumall[1][i];
        float wpv = w0 * pm + w1 * pp;
        float wn = w0 * (sm - pm) + w1 * (sp - pp);
        float nei = fmaxf(g_rowsum[0][i] + g_rowsum[1][i], 1.0f);
        float ratio = wpv / (wpv + wn) / nei;
        ratio = fmaxf(ratio, 1e-10f);
        term += -logf(ratio);
    }
    __shared__ float red[256];
    red[threadIdx.x] = term;
    __syncthreads();
#pragma unroll
    for (int s = 128; s > 0; s >>= 1) {
        if (threadIdx.x < s) red[threadIdx.x] += red[threadIdx.x + s];
        __syncthreads();
    }
    if (threadIdx.x == 0) atomicAdd(&g_loss_acc, red[0]);
}

__global__ void k_finalize(float* __restrict__ out) {
    out[0] = g_loss_acc / (float)N;
}

// ---------------- launch (fork-join overlap) ----------------
extern "C" void kernel_launch(void* const* d_in, const int* in_sizes, int n_in,
                              void* d_out, int out_size) {
    const float* embF = (const float*)d_in[0];
    const float* embM = (const float*)d_in[1];
    const float* embP = (const float*)d_in[2];
    const float* FM_adj = (const float*)d_in[3];
    const float* FP_adj = (const float*)d_in[4];
    const float* W1 = (const float*)d_in[5];
    const float* b1 = (const float*)d_in[6];
    const float* W2 = (const float*)d_in[7];
    const float* b2 = (const float*)d_in[8];
    float* out = (float*)d_out;

    static cudaStream_t s1 = nullptr;
    static cudaEvent_t evA = nullptr, evB = nullptr;
    static bool attr_set = false;
    if (!attr_set) {
        cudaStreamCreateWithFlags(&s1, cudaStreamNonBlocking);
        cudaEventCreateWithFlags(&evA, cudaEventDisableTiming);
        cudaEventCreateWithFlags(&evB, cudaEventDisableTiming);
        cudaFuncSetAttribute(k_simsum_mma, cudaFuncAttributeMaxDynamicSharedMemorySize, SIMTC_SMEM);
        cudaFuncSetAttribute(k_mlp, cudaFuncAttributeMaxDynamicSharedMemorySize, MLP_SMEM);
        attr_set = true;
    }

    k_zero<<<(2 * N + 255) / 256, 256>>>();
    k_normalize<<<dim3(N, 3), 128>>>(embF, embM, embP);
    cudaEventRecord(evA, 0);

    // main branch: tensor-core sim sums (launch first; 2 CTAs/SM, ~139KB smem,
    // leaving room for repr_pos blocks to co-schedule)
    k_simsum_mma<<<dim3(N / 128, JSPLIT), 256, SIMTC_SMEM>>>();

    // side branch: adjacency scan + MLP (DRAM-bound; overlaps tensor work)
    cudaStreamWaitEvent(s1, evA, 0);
    k_repr_pos<<<dim3(N, 2), 128, 0, s1>>>(FM_adj, FP_adj, embM, embP);
    k_mlp<<<N / MLP_ROWS, 256, MLP_SMEM, s1>>>(W1, b1, W2, b2, out + 1);
    cudaEventRecord(evB, s1);

    cudaStreamWaitEvent(0, evB, 0);
    k_loss<<<24, 256>>>();
    k_finalize<<<1, 1>>>(out);
}